// round 15
// baseline (speedup 1.0000x reference)
#include <cuda_runtime.h>
#include <cuda_bf16.h>
#include <math.h>
#include <stdint.h>

#define NVOX   (64*64*64)
#define BATCH  2
#define NPART  32768
#define CIN    4
#define CMID   32
#define COUTC  4

// ---------------- device global scratch (no allocation allowed) ------------
__device__ float g_grid0[BATCH*CIN *NVOX];   // splat out [B,4,64,64,64] NCDHW
__device__ float g_bufA [BATCH*CMID*NVOX];   // layer2 f32 NCDHW out -> layer3 in
__device__ float g_out4 [BATCH*COUTC*NVOX];  // layer3 out

// split bf16 activations, layout [b][x][y][z][hi(32)|lo(32)] (128B per voxel)
__device__ __nv_bfloat16 g_s0[(size_t)BATCH*NVOX*64];
__device__ __nv_bfloat16 g_s1[(size_t)BATCH*NVOX*64];
// pre-split weights, layout [tap(27)][co(32)][hi 32 | lo 32] bf16 (128B per co)
__device__ __nv_bfloat16 g_w1p[27*32*64];
__device__ __nv_bfloat16 g_w2p[27*32*64];

__device__ __forceinline__ float* buf_ptr(int s) {
    switch (s) { case 0: return g_grid0; case 1: return g_bufA;
                 default: return g_out4; }
}

// ---------------- packed fp32x2 helpers ------------------------------------
__device__ __forceinline__ unsigned long long bcast2(float v) {
    unsigned long long r; unsigned int b = __float_as_uint(v);
    asm("mov.b64 %0, {%1, %1};" : "=l"(r) : "r"(b));
    return r;
}
__device__ __forceinline__ void ffma2(unsigned long long& acc,
                                      unsigned long long a, unsigned long long b) {
    asm("fma.rn.f32x2 %0, %1, %2, %0;" : "+l"(acc) : "l"(a), "l"(b));
}
__device__ __forceinline__ void unpack2(unsigned long long v, float& lo, float& hi) {
    unsigned int l, h;
    asm("mov.b64 {%0, %1}, %2;" : "=r"(l), "=r"(h) : "l"(v));
    lo = __uint_as_float(l); hi = __uint_as_float(h);
}

// ---------------- mma.sync / ldmatrix helpers (sm_80+, OK on sm_103) -------
__device__ __forceinline__ uint32_t smem_u32(const void* p) {
    uint32_t a;
    asm("{ .reg .u64 t; cvta.to.shared.u64 t, %1; cvt.u32.u64 %0, t; }"
        : "=r"(a) : "l"(p));
    return a;
}
__device__ __forceinline__ void ldsm4(uint32_t* r, uint32_t a) {
    asm volatile("ldmatrix.sync.aligned.m8n8.x4.shared.b16 {%0,%1,%2,%3}, [%4];"
        : "=r"(r[0]), "=r"(r[1]), "=r"(r[2]), "=r"(r[3]) : "r"(a));
}
__device__ __forceinline__ void mma16816(float* d, const uint32_t* a,
                                         const uint32_t* b) {
    asm volatile("mma.sync.aligned.m16n8k16.row.col.f32.bf16.bf16.f32 "
        "{%0,%1,%2,%3}, {%4,%5,%6,%7}, {%8,%9}, {%0,%1,%2,%3};"
        : "+f"(d[0]), "+f"(d[1]), "+f"(d[2]), "+f"(d[3])
        : "r"(a[0]), "r"(a[1]), "r"(a[2]), "r"(a[3]), "r"(b[0]), "r"(b[1]));
}
#define SWZ(o) ((o) ^ (((o) >> 3) & 0x70))

__device__ __forceinline__ uint32_t packbf(__nv_bfloat16 a, __nv_bfloat16 b) {
    unsigned short ua = *reinterpret_cast<unsigned short*>(&a);
    unsigned short ub = *reinterpret_cast<unsigned short*>(&b);
    return (uint32_t)ua | ((uint32_t)ub << 16);
}

// ---------------------------------------------------------------------------
__global__ void zero_grid0_kernel() {
    int n = BATCH * CIN * NVOX;
    for (int i = blockIdx.x * blockDim.x + threadIdx.x; i < n;
         i += gridDim.x * blockDim.x)
        g_grid0[i] = 0.0f;
}

// ---------------------------------------------------------------------------
__global__ void splat_kernel(const float* __restrict__ locs,
                             const float* __restrict__ data,
                             const float* __restrict__ dens) {
    int p = blockIdx.x * blockDim.x + threadIdx.x;
    if (p >= BATCH * NPART) return;
    int b = p / NPART;
    float lx = locs[3*p+0], ly = locs[3*p+1], lz = locs[3*p+2];
    float inv = 1.0f / dens[p];
    float d0 = data[4*p+0]*inv, d1 = data[4*p+1]*inv;
    float d2c = data[4*p+2]*inv, d3 = data[4*p+3]*inv;
    const float STEP = 0.015625f, INVSTEP = 64.0f, H2 = 0.0009765625f;
    const float C6 = (float)(315.0 / (64.0 * 3.14159265358979323846 *
                                      2.8421709430404007e-14));
    int bx = (int)floorf(lx * INVSTEP);
    int by = (int)floorf(ly * INVSTEP);
    int bz = (int)floorf(lz * INVSTEP);
    float* gb = g_grid0 + (size_t)b * CIN * NVOX;
    for (int ox = -2; ox <= 2; ++ox) {
        int cx = bx + ox; if ((unsigned)cx >= 64u) continue;
        float ddx = ((float)cx + 0.5f) * STEP - lx;
        float sx = ddx * ddx;
        for (int oy = -2; oy <= 2; ++oy) {
            int cy = by + oy; if ((unsigned)cy >= 64u) continue;
            float ddy = ((float)cy + 0.5f) * STEP - ly;
            float sxy = sx + ddy * ddy;
            if (sxy > H2) continue;
            for (int oz = -2; oz <= 2; ++oz) {
                int cz = bz + oz; if ((unsigned)cz >= 64u) continue;
                float ddz = ((float)cz + 0.5f) * STEP - lz;
                float dd2 = sxy + ddz * ddz;
                if (dd2 > H2) continue;
                float t = H2 - dd2;
                float w = C6 * t * t * t;
                int flat = ((cx << 6) + cy) * 64 + cz;
                atomicAdd(gb + 0*NVOX + flat, w * d0);
                atomicAdd(gb + 1*NVOX + flat, w * d1);
                atomicAdd(gb + 2*NVOX + flat, w * d2c);
                atomicAdd(gb + 3*NVOX + flat, w * d3);
            }
        }
    }
}

// ---------------------------------------------------------------------------
// FFMA2 direct conv (R8 proven). OUTMODE: 0 = f32 NCDHW, 1 = split bf16.
// ---------------------------------------------------------------------------
template <int CI, int CO, int CO_PER, bool PRELU, int OUTMODE>
__global__ void __launch_bounds__(128 * (CO / CO_PER), 2)
conv3d_kernel(int in_sel, int out_sel,
              const float* __restrict__ W,
              const float* __restrict__ bias,
              const float* __restrict__ alpha) {
    constexpr int NP     = CO_PER / 2;
    constexpr int NT     = 128 * (CO / CO_PER);
    constexpr int WCHUNK = (CI < 16) ? CI : 16;
    constexpr int WELEMS = WCHUNK * 27 * CO;
    constexpr int NLOAD  = (1000 + NT - 1) / NT;

    const float* in  = buf_ptr(in_sel);
    float*       out = buf_ptr(out_sel);

    int tid = threadIdx.x;
    int x = tid & 7, y = (tid >> 3) & 7, zg = (tid >> 6) & 1, cog = tid >> 7;
    int bidx = blockIdx.x;
    int tz = bidx & 7, ty = (bidx >> 3) & 7, tx = (bidx >> 6) & 7;
    int b  = bidx >> 9;
    int ox = tx << 3, oy = ty << 3, oz = tz << 3;
    int z0 = zg << 2;

    __shared__ __align__(16) float s_tile[2][1000];
    __shared__ __align__(16) float s_w[WELEMS];

    int offs[NLOAD];
#pragma unroll
    for (int k = 0; k < NLOAD; ++k) {
        int i = tid + k * NT;
        offs[k] = -1;
        if (i < 1000) {
            int lz = i % 10; int r = i / 10; int ly = r % 10; int lx = r / 10;
            int gx = ox + lx - 1, gy = oy + ly - 1, gz = oz + lz - 1;
            if ((unsigned)gx < 64u && (unsigned)gy < 64u && (unsigned)gz < 64u)
                offs[k] = (((gx << 6) + gy) << 6) + gz;
        }
    }

    unsigned long long acc2[4][NP];
#pragma unroll
    for (int t = 0; t < 4; ++t)
#pragma unroll
        for (int j = 0; j < NP; ++j) acc2[t][j] = 0ULL;

    const float* inb = in + (size_t)b * CI * NVOX;
    const int cobase = cog * CO_PER;

    float pv[NLOAD];
#pragma unroll
    for (int k = 0; k < NLOAD; ++k)
        pv[k] = (offs[k] >= 0) ? __ldg(inb + offs[k]) : 0.0f;
#pragma unroll
    for (int k = 0; k < NLOAD; ++k) {
        int i = tid + k * NT;
        if (i < 1000) s_tile[0][i] = pv[k];
    }

    int cur = 0;
    for (int ci = 0; ci < CI; ++ci) {
        int c = ci % WCHUNK;
        if (c == 0) {
            if (ci > 0) __syncthreads();
            int chunk = ci / WCHUNK;
            for (int i = tid; i < WELEMS; i += NT) {
                int co = i % CO; int t2 = i / CO;
                int tap = t2 % 27; int cc = t2 / 27;
                s_w[i] = W[co * (CI * 27) + (chunk * WCHUNK + cc) * 27 + tap];
            }
        }
        __syncthreads();

        if (ci + 1 < CI) {
            const float* incn = inb + (ci + 1) * NVOX;
#pragma unroll
            for (int k = 0; k < NLOAD; ++k)
                pv[k] = (offs[k] >= 0) ? __ldg(incn + offs[k]) : 0.0f;
        }

        const float* tile = s_tile[cur];
        const float* swc  = s_w + c * 27 * CO;
#pragma unroll
        for (int dx = 0; dx < 3; ++dx) {
#pragma unroll
            for (int dy = 0; dy < 3; ++dy) {
                const float* tp = tile + ((x + dx) * 10 + (y + dy)) * 10 + z0;
                float2 p0 = *reinterpret_cast<const float2*>(tp + 0);
                float2 p1 = *reinterpret_cast<const float2*>(tp + 2);
                float2 p2 = *reinterpret_cast<const float2*>(tp + 4);
                unsigned long long vb[6];
                vb[0] = bcast2(p0.x); vb[1] = bcast2(p0.y);
                vb[2] = bcast2(p1.x); vb[3] = bcast2(p1.y);
                vb[4] = bcast2(p2.x); vb[5] = bcast2(p2.y);
#pragma unroll
                for (int dz = 0; dz < 3; ++dz) {
                    int tap = (dx * 3 + dy) * 3 + dz;
                    const unsigned long long* wp =
                        reinterpret_cast<const unsigned long long*>(
                            swc + tap * CO + cobase);
                    unsigned long long wr[NP];
#pragma unroll
                    for (int j = 0; j < NP; ++j) wr[j] = wp[j];
#pragma unroll
                    for (int t = 0; t < 4; ++t)
#pragma unroll
                        for (int j = 0; j < NP; ++j)
                            ffma2(acc2[t][j], vb[t + dz], wr[j]);
                }
            }
        }

        if (ci + 1 < CI) {
#pragma unroll
            for (int k = 0; k < NLOAD; ++k) {
                int i = tid + k * NT;
                if (i < 1000) s_tile[cur ^ 1][i] = pv[k];
            }
            cur ^= 1;
        }
    }

    float a = 0.0f;
    if (PRELU) a = alpha[0];

    if (OUTMODE == 1) {
        // interleaved split bf16 out: g_s0[(b*NVOX+sp)*64 + co] (hi), +32 (lo)
#pragma unroll
        for (int t = 0; t < 4; ++t) {
            __align__(16) __nv_bfloat16 hv[CO_PER], lv[CO_PER];
#pragma unroll
            for (int j = 0; j < NP; ++j) {
                int co0 = cobase + 2 * j;
                float lo, hi;
                unpack2(acc2[t][j], lo, hi);
                lo += bias[co0]; hi += bias[co0 + 1];
                if (PRELU) {
                    lo = (lo >= 0.0f) ? lo : a * lo;
                    hi = (hi >= 0.0f) ? hi : a * hi;
                }
                __nv_bfloat16 h0 = __float2bfloat16(lo);
                __nv_bfloat16 h1 = __float2bfloat16(hi);
                hv[2*j]   = h0; lv[2*j]   = __float2bfloat16(lo - __bfloat162float(h0));
                hv[2*j+1] = h1; lv[2*j+1] = __float2bfloat16(hi - __bfloat162float(h1));
            }
            size_t sp = ((((size_t)(ox + x) << 6) + (oy + y)) << 6) + oz + z0 + t;
            size_t o = ((size_t)b * NVOX + sp) * 64 + cobase;
            *reinterpret_cast<uint4*>(g_s0 + o)      = *reinterpret_cast<uint4*>(hv);
            *reinterpret_cast<uint4*>(g_s0 + o + 32) = *reinterpret_cast<uint4*>(lv);
        }
    } else {
#pragma unroll
        for (int j = 0; j < NP; ++j) {
            int co0 = cobase + 2 * j;
            float bb0 = bias[co0], bb1 = bias[co0 + 1];
            float r0[4], r1[4];
#pragma unroll
            for (int t = 0; t < 4; ++t) {
                float lo, hi;
                unpack2(acc2[t][j], lo, hi);
                lo += bb0; hi += bb1;
                if (PRELU) {
                    lo = (lo >= 0.0f) ? lo : a * lo;
                    hi = (hi >= 0.0f) ? hi : a * hi;
                }
                r0[t] = lo; r1[t] = hi;
            }
            size_t sp = ((((size_t)(ox + x) << 6) + (oy + y)) << 6) + oz + z0;
            size_t o0 = (size_t)(b * CO + co0) * NVOX + sp;
            *reinterpret_cast<float4*>(out + o0) =
                make_float4(r0[0], r0[1], r0[2], r0[3]);
            *reinterpret_cast<float4*>(out + o0 + NVOX) =
                make_float4(r1[0], r1[1], r1[2], r1[3]);
        }
    }
}

// ---------------------------------------------------------------------------
// Weight prep: split fp32 W[co][ci][27] into bf16 hi/lo [tap][co][hi32|lo32]
// ---------------------------------------------------------------------------
__global__ void wprep_kernel(const float* __restrict__ W, int sel) {
    __nv_bfloat16* wp = (sel == 1) ? g_w1p : g_w2p;
    int i = blockIdx.x * blockDim.x + threadIdx.x;
    if (i >= 27 * 32 * 32) return;
    int tap = i >> 10, r = i & 1023, co = r >> 5, ci = r & 31;
    float w = W[co * (32 * 27) + ci * 27 + tap];
    __nv_bfloat16 h = __float2bfloat16(w);
    wp[(tap * 32 + co) * 64 + ci] = h;
    wp[(tap * 32 + co) * 64 + 32 + ci] = __float2bfloat16(w - __bfloat162float(h));
}

// ---------------------------------------------------------------------------
// mma.sync bf16-split implicit-GEMM conv 32->32 + PReLU.  BARRIER-FREE loop:
// Block: 256 thr (8 warps). Tile: x fixed, 2y x 64z = M=128 rows, N=32 co.
// A region (3x * 4y * 64z voxels, 128B [hi|lo]) staged once     =  96 KB smem
// ALL 27 taps of W staged once (27 x 4KB)                       = 108 KB smem
// -> the 27-tap MMA loop reads read-only smem with NO __syncthreads.
// Warp w handles rows m = w*16..w*16+15 (one m16 tile).
// Lo-half ldmatrix addresses use SWZ(o+64) — NOT SWZ(o)+64 (carry corrupts).
// ---------------------------------------------------------------------------
#define A_BYTES (768 * 128)                  // 98304
#define W_OFF   A_BYTES
#define Z_OFF   (A_BYTES + 27 * 4096)        // zero rows (256B)
#define TC_SMEM (A_BYTES + 27 * 4096 + 256)  // 209152

template <int LAYER>
__global__ void __launch_bounds__(256, 1)
tconv_kernel(const float* __restrict__ bias, const float* __restrict__ alpha) {
    const __nv_bfloat16* in = (LAYER == 1) ? g_s0 : g_s1;
    const __nv_bfloat16* wp = (LAYER == 1) ? g_w1p : g_w2p;

    extern __shared__ __align__(1024) char smem[];
    uint32_t sb = smem_u32(smem);

    int tid = threadIdx.x, lane = tid & 31, w = tid >> 5;
    int bidx = blockIdx.x;
    int x = bidx & 63, yg = (bidx >> 6) & 31, b = bidx >> 11;
    int oy = yg << 1;

    // ---- stage A region: voxel u = (xi*4 + yi)*64 + zi, 8 chunks of 16B ----
    {
        const __nv_bfloat16* inb = in + (size_t)b * NVOX * 64;
#pragma unroll 4
        for (int i = tid; i < 768 * 8; i += 256) {
            int u = i >> 3, ch = i & 7;
            int xi = u >> 8, rem = u & 255;
            int yi = rem >> 6, zi = rem & 63;
            int gx = x + xi - 1, gy = oy + yi - 1;
            uint4 v = make_uint4(0, 0, 0, 0);
            if ((unsigned)gx < 64u && (unsigned)gy < 64u)
                v = *reinterpret_cast<const uint4*>(
                    inb + ((((size_t)(gx << 6) + gy) << 6) + zi) * 64 + ch * 8);
            uint32_t d = sb + SWZ((uint32_t)(u * 128 + ch * 16));
            asm volatile("st.shared.v4.b32 [%0], {%1,%2,%3,%4};"
                         :: "r"(d), "r"(v.x), "r"(v.y), "r"(v.z), "r"(v.w)
                         : "memory");
        }
    }
    // ---- stage ALL W taps: 27*32 rows x 8 chunks = 6912 uint4 ----
    {
#pragma unroll 4
        for (int i = tid; i < 27 * 32 * 8; i += 256) {
            int row = i >> 3, ch = i & 7;       // row = tap*32 + co
            int tap = row >> 5, co = row & 31;
            uint4 v = *reinterpret_cast<const uint4*>(
                wp + (size_t)row * 64 + ch * 8);
            uint32_t d = sb + W_OFF + (uint32_t)(tap * 4096) +
                         SWZ((uint32_t)(co * 128 + ch * 16));
            asm volatile("st.shared.v4.b32 [%0], {%1,%2,%3,%4};"
                         :: "r"(d), "r"(v.x), "r"(v.y), "r"(v.z), "r"(v.w)
                         : "memory");
        }
    }
    if (tid < 16) {
        uint32_t d = sb + Z_OFF + tid * 16;
        asm volatile("st.shared.v4.b32 [%0], {%1,%1,%1,%1};"
                     :: "r"(d), "r"(0u) : "memory");
    }
    __syncthreads();   // the ONLY block barrier before the epilogue

    // ---- per-lane invariants ----
    int r15 = lane & 15, kc = lane >> 4;
    int m0 = w * 16 + r15;
    uint32_t laneA = (uint32_t)((m0 >> 6) * 8192);
    int zm1 = (m0 & 63) - 1;
    // W ldmatrix lane bases (hi and lo swizzled separately)
    int wco = (lane & 7) + ((lane >> 4) << 3);
    int cadd = (lane >> 3) & 1;
    uint32_t wbh[2][2], wbl[2][2];
#pragma unroll
    for (int ks = 0; ks < 2; ++ks)
#pragma unroll
        for (int h = 0; h < 2; ++h) {
            int co = wco + h * 16;
            uint32_t o = (uint32_t)(co * 128 + (ks * 2 + cadd) * 16);
            wbh[ks][h] = SWZ(o);
            wbl[ks][h] = SWZ(o + 64);
        }

    float acc[4][4];
#pragma unroll
    for (int nt = 0; nt < 4; ++nt)
#pragma unroll
        for (int q = 0; q < 4; ++q) acc[nt][q] = 0.0f;

    // ---- tap loop: NO barriers ----
    for (int t = 0; t < 27; ++t) {
        int dz = t % 3, dy = (t / 3) % 3, dx = t / 9;
        uint32_t tapoff = (uint32_t)(dx * 32768 + dy * 8192);

        // A fragments
        uint32_t ahf[2][4], alf[2][4];
        {
            int zs = zm1 + dz;
            bool ok = (unsigned)zs < 64u;
            uint32_t vox = tapoff + laneA + (uint32_t)(zs * 128);
#pragma unroll
            for (int ks = 0; ks < 2; ++ks) {
                uint32_t o  = vox + (uint32_t)((ks * 2 + kc) * 16);
                uint32_t ah = ok ? sb + SWZ(o)      : sb + Z_OFF;
                uint32_t al = ok ? sb + SWZ(o + 64) : sb + Z_OFF + 64;
                ldsm4(ahf[ks], ah);
                ldsm4(alf[ks], al);
            }
        }
        // W fragments (resident smem, per tap)
        uint32_t whf[2][8], wlf[2][8];
        {
            uint32_t wbuf = sb + W_OFF + (uint32_t)(t * 4096);
#pragma unroll
            for (int ks = 0; ks < 2; ++ks)
#pragma unroll
                for (int h = 0; h < 2; ++h) {
                    ldsm4(&whf[ks][h * 4], wbuf + wbh[ks][h]);
                    ldsm4(&wlf[ks][h * 4], wbuf + wbl[ks][h]);
                }
        }
        // mma: Ah*Wh + Al*Wh + Ah*Wl
#pragma unroll
        for (int nt = 0; nt < 4; ++nt) {
            float* d = acc[nt];
#pragma unroll
            for (int ks = 0; ks < 2; ++ks) {
                mma16816(d, ahf[ks], &whf[ks][nt * 2]);
                mma16816(d, alf[ks], &whf[ks][nt * 2]);
                mma16816(d, ahf[ks], &wlf[ks][nt * 2]);
            }
        }
    }

    // ---- epilogue: bias + PReLU; LAYER 1 -> split bf16 g_s1, LAYER 2 -> f32
    float a = alpha[0];
#pragma unroll
    for (int rr = 0; rr < 2; ++rr) {
        int m = w * 16 + (lane >> 2) + rr * 8;
        int yb = m >> 6, z = m & 63;
        size_t sp = (((size_t)(x << 6) + (oy + yb)) << 6) + z;
#pragma unroll
        for (int nt = 0; nt < 4; ++nt) {
            int c = nt * 8 + (lane & 3) * 2;
            float v0 = acc[nt][rr * 2 + 0] + __ldg(bias + c);
            float v1 = acc[nt][rr * 2 + 1] + __ldg(bias + c + 1);
            v0 = (v0 >= 0.0f) ? v0 : a * v0;
            v1 = (v1 >= 0.0f) ? v1 : a * v1;
            if (LAYER == 1) {
                __nv_bfloat16 h0 = __float2bfloat16(v0);
                __nv_bfloat16 h1 = __float2bfloat16(v1);
                __nv_bfloat16 l0 = __float2bfloat16(v0 - __bfloat162float(h0));
                __nv_bfloat16 l1 = __float2bfloat16(v1 - __bfloat162float(h1));
                size_t o = ((size_t)b * NVOX + sp) * 64 + c;
                *reinterpret_cast<uint32_t*>(g_s1 + o)      = packbf(h0, h1);
                *reinterpret_cast<uint32_t*>(g_s1 + o + 32) = packbf(l0, l1);
            } else {
                g_bufA[((size_t)(b * 32 + c))     * NVOX + sp] = v0;
                g_bufA[((size_t)(b * 32 + c + 1)) * NVOX + sp] = v1;
            }
        }
    }
}

// ---------------------------------------------------------------------------
__global__ void gather_kernel(const float* __restrict__ locs,
                              float* __restrict__ out) {
    int p = blockIdx.x * blockDim.x + threadIdx.x;
    if (p >= BATCH * NPART) return;
    int b = p / NPART;
    const float* g = g_out4 + (size_t)b * COUTC * NVOX;
    float px = locs[3*p+0] * 64.0f - 0.5f;
    float py = locs[3*p+1] * 64.0f - 0.5f;
    float pz = locs[3*p+2] * 64.0f - 0.5f;
    int ix = (int)floorf(px), iy = (int)floorf(py), iz = (int)floorf(pz);
    float fx = px - (float)ix, fy = py - (float)iy, fz = pz - (float)iz;
    float r0 = 0.f, r1 = 0.f, r2 = 0.f, r3 = 0.f;
#pragma unroll
    for (int dx = 0; dx < 2; ++dx) {
        int jx = ix + dx;
        float wx = dx ? fx : 1.0f - fx;
#pragma unroll
        for (int dy = 0; dy < 2; ++dy) {
            int jy = iy + dy;
            float wxy = wx * (dy ? fy : 1.0f - fy);
#pragma unroll
            for (int dz = 0; dz < 2; ++dz) {
                int jz = iz + dz;
                float w = wxy * (dz ? fz : 1.0f - fz);
                if ((unsigned)jx < 64u && (unsigned)jy < 64u && (unsigned)jz < 64u) {
                    int flat = ((jx << 6) + jy) * 64 + jz;
                    r0 += w * g[0*NVOX + flat];
                    r1 += w * g[1*NVOX + flat];
                    r2 += w * g[2*NVOX + flat];
                    r3 += w * g[3*NVOX + flat];
                }
            }
        }
    }
    out[4*p+0] = r0; out[4*p+1] = r1; out[4*p+2] = r2; out[4*p+3] = r3;
}

// ---------------------------------------------------------------------------
extern "C" void kernel_launch(void* const* d_in, const int* in_sizes, int n_in,
                              void* d_out, int out_size) {
    const float* locs = (const float*)d_in[0];
    const float* data = (const float*)d_in[1];
    const float* dens = (const float*)d_in[2];
    const float* W0 = (const float*)d_in[3];
    const float* b0 = (const float*)d_in[4];
    const float* W1 = (const float*)d_in[5];
    const float* b1 = (const float*)d_in[6];
    const float* W2 = (const float*)d_in[7];
    const float* b2 = (const float*)d_in[8];
    const float* W3 = (const float*)d_in[9];
    const float* b3 = (const float*)d_in[10];
    const float* a0 = (const float*)d_in[11];
    const float* a1 = (const float*)d_in[12];
    const float* a2 = (const float*)d_in[13];
    float* out = (float*)d_out;
    (void)in_sizes; (void)n_in; (void)out_size;

    cudaFuncSetAttribute(tconv_kernel<1>,
                         cudaFuncAttributeMaxDynamicSharedMemorySize, TC_SMEM);
    cudaFuncSetAttribute(tconv_kernel<2>,
                         cudaFuncAttributeMaxDynamicSharedMemorySize, TC_SMEM);

    zero_grid0_kernel<<<512, 256>>>();
    splat_kernel<<<(BATCH * NPART + 127) / 128, 128>>>(locs, data, dens);

    wprep_kernel<<<108, 256>>>(W1, 1);
    wprep_kernel<<<108, 256>>>(W2, 2);

    // layer0: FFMA2 conv -> split bf16 g_s0
    conv3d_kernel<CIN, CMID, 8, true, 1><<<1024, 512>>>(0, 1, W0, b0, a0);
    // layers 1,2: mma.sync bf16-split implicit GEMM (barrier-free tap loop)
    tconv_kernel<1><<<4096, 256, TC_SMEM>>>(b1, a1);
    tconv_kernel<2><<<4096, 256, TC_SMEM>>>(b2, a2);
    // layer3: FFMA2 conv, g_bufA -> g_out4
    conv3d_kernel<CMID, COUTC, 2, false, 0><<<1024, 256>>>(1, 2, W3, b3, a0);

    gather_kernel<<<(BATCH * NPART + 127) / 128, 128>>>(locs, out);
}

// round 16
// speedup vs baseline: 1.1571x; 1.1571x over previous
#include <cuda_runtime.h>
#include <cuda_bf16.h>
#include <math.h>
#include <stdint.h>

#define NVOX   (64*64*64)
#define BATCH  2
#define NPART  32768
#define CIN    4
#define CMID   32
#define COUTC  4

// ---------------- device global scratch (no allocation allowed) ------------
__device__ float g_grid0[BATCH*CIN *NVOX];   // splat out [B,4,64,64,64] NCDHW
__device__ float g_bufA [BATCH*CMID*NVOX];   // layer2 f32 NCDHW out -> layer3 in
__device__ float g_out4 [BATCH*COUTC*NVOX];  // layer3 out

// split bf16 activations, layout [b][x][y][z][hi(32)|lo(32)] (128B per voxel)
__device__ __nv_bfloat16 g_s0[(size_t)BATCH*NVOX*64];
__device__ __nv_bfloat16 g_s1[(size_t)BATCH*NVOX*64];
// pre-split weights, layout [tap(27)][co(32)][hi 32 | lo 32] bf16 (128B per co)
__device__ __nv_bfloat16 g_w1p[27*32*64];
__device__ __nv_bfloat16 g_w2p[27*32*64];

__device__ __forceinline__ float* buf_ptr(int s) {
    switch (s) { case 0: return g_grid0; case 1: return g_bufA;
                 default: return g_out4; }
}

// ---------------- packed fp32x2 helpers ------------------------------------
__device__ __forceinline__ unsigned long long bcast2(float v) {
    unsigned long long r; unsigned int b = __float_as_uint(v);
    asm("mov.b64 %0, {%1, %1};" : "=l"(r) : "r"(b));
    return r;
}
__device__ __forceinline__ void ffma2(unsigned long long& acc,
                                      unsigned long long a, unsigned long long b) {
    asm("fma.rn.f32x2 %0, %1, %2, %0;" : "+l"(acc) : "l"(a), "l"(b));
}
__device__ __forceinline__ void unpack2(unsigned long long v, float& lo, float& hi) {
    unsigned int l, h;
    asm("mov.b64 {%0, %1}, %2;" : "=r"(l), "=r"(h) : "l"(v));
    lo = __uint_as_float(l); hi = __uint_as_float(h);
}

// ---------------- mma.sync / ldmatrix helpers (sm_80+, OK on sm_103) -------
__device__ __forceinline__ uint32_t smem_u32(const void* p) {
    uint32_t a;
    asm("{ .reg .u64 t; cvta.to.shared.u64 t, %1; cvt.u32.u64 %0, t; }"
        : "=r"(a) : "l"(p));
    return a;
}
__device__ __forceinline__ void ldsm4(uint32_t* r, uint32_t a) {
    asm volatile("ldmatrix.sync.aligned.m8n8.x4.shared.b16 {%0,%1,%2,%3}, [%4];"
        : "=r"(r[0]), "=r"(r[1]), "=r"(r[2]), "=r"(r[3]) : "r"(a));
}
__device__ __forceinline__ void mma16816(float* d, const uint32_t* a,
                                         const uint32_t* b) {
    asm volatile("mma.sync.aligned.m16n8k16.row.col.f32.bf16.bf16.f32 "
        "{%0,%1,%2,%3}, {%4,%5,%6,%7}, {%8,%9}, {%0,%1,%2,%3};"
        : "+f"(d[0]), "+f"(d[1]), "+f"(d[2]), "+f"(d[3])
        : "r"(a[0]), "r"(a[1]), "r"(a[2]), "r"(a[3]), "r"(b[0]), "r"(b[1]));
}
#define SWZ(o) ((o) ^ (((o) >> 3) & 0x70))

__device__ __forceinline__ uint32_t packbf(__nv_bfloat16 a, __nv_bfloat16 b) {
    unsigned short ua = *reinterpret_cast<unsigned short*>(&a);
    unsigned short ub = *reinterpret_cast<unsigned short*>(&b);
    return (uint32_t)ua | ((uint32_t)ub << 16);
}

// ---------------------------------------------------------------------------
__global__ void zero_grid0_kernel() {
    int n = BATCH * CIN * NVOX;
    for (int i = blockIdx.x * blockDim.x + threadIdx.x; i < n;
         i += gridDim.x * blockDim.x)
        g_grid0[i] = 0.0f;
}

// ---------------------------------------------------------------------------
__global__ void splat_kernel(const float* __restrict__ locs,
                             const float* __restrict__ data,
                             const float* __restrict__ dens) {
    int p = blockIdx.x * blockDim.x + threadIdx.x;
    if (p >= BATCH * NPART) return;
    int b = p / NPART;
    float lx = locs[3*p+0], ly = locs[3*p+1], lz = locs[3*p+2];
    float inv = 1.0f / dens[p];
    float d0 = data[4*p+0]*inv, d1 = data[4*p+1]*inv;
    float d2c = data[4*p+2]*inv, d3 = data[4*p+3]*inv;
    const float STEP = 0.015625f, INVSTEP = 64.0f, H2 = 0.0009765625f;
    const float C6 = (float)(315.0 / (64.0 * 3.14159265358979323846 *
                                      2.8421709430404007e-14));
    int bx = (int)floorf(lx * INVSTEP);
    int by = (int)floorf(ly * INVSTEP);
    int bz = (int)floorf(lz * INVSTEP);
    float* gb = g_grid0 + (size_t)b * CIN * NVOX;
    for (int ox = -2; ox <= 2; ++ox) {
        int cx = bx + ox; if ((unsigned)cx >= 64u) continue;
        float ddx = ((float)cx + 0.5f) * STEP - lx;
        float sx = ddx * ddx;
        for (int oy = -2; oy <= 2; ++oy) {
            int cy = by + oy; if ((unsigned)cy >= 64u) continue;
            float ddy = ((float)cy + 0.5f) * STEP - ly;
            float sxy = sx + ddy * ddy;
            if (sxy > H2) continue;
            for (int oz = -2; oz <= 2; ++oz) {
                int cz = bz + oz; if ((unsigned)cz >= 64u) continue;
                float ddz = ((float)cz + 0.5f) * STEP - lz;
                float dd2 = sxy + ddz * ddz;
                if (dd2 > H2) continue;
                float t = H2 - dd2;
                float w = C6 * t * t * t;
                int flat = ((cx << 6) + cy) * 64 + cz;
                atomicAdd(gb + 0*NVOX + flat, w * d0);
                atomicAdd(gb + 1*NVOX + flat, w * d1);
                atomicAdd(gb + 2*NVOX + flat, w * d2c);
                atomicAdd(gb + 3*NVOX + flat, w * d3);
            }
        }
    }
}

// ---------------------------------------------------------------------------
// FFMA2 direct conv (R8 proven). OUTMODE: 0 = f32 NCDHW, 1 = split bf16.
// ---------------------------------------------------------------------------
template <int CI, int CO, int CO_PER, bool PRELU, int OUTMODE>
__global__ void __launch_bounds__(128 * (CO / CO_PER), 2)
conv3d_kernel(int in_sel, int out_sel,
              const float* __restrict__ W,
              const float* __restrict__ bias,
              const float* __restrict__ alpha) {
    constexpr int NP     = CO_PER / 2;
    constexpr int NT     = 128 * (CO / CO_PER);
    constexpr int WCHUNK = (CI < 16) ? CI : 16;
    constexpr int WELEMS = WCHUNK * 27 * CO;
    constexpr int NLOAD  = (1000 + NT - 1) / NT;

    const float* in  = buf_ptr(in_sel);
    float*       out = buf_ptr(out_sel);

    int tid = threadIdx.x;
    int x = tid & 7, y = (tid >> 3) & 7, zg = (tid >> 6) & 1, cog = tid >> 7;
    int bidx = blockIdx.x;
    int tz = bidx & 7, ty = (bidx >> 3) & 7, tx = (bidx >> 6) & 7;
    int b  = bidx >> 9;
    int ox = tx << 3, oy = ty << 3, oz = tz << 3;
    int z0 = zg << 2;

    __shared__ __align__(16) float s_tile[2][1000];
    __shared__ __align__(16) float s_w[WELEMS];

    int offs[NLOAD];
#pragma unroll
    for (int k = 0; k < NLOAD; ++k) {
        int i = tid + k * NT;
        offs[k] = -1;
        if (i < 1000) {
            int lz = i % 10; int r = i / 10; int ly = r % 10; int lx = r / 10;
            int gx = ox + lx - 1, gy = oy + ly - 1, gz = oz + lz - 1;
            if ((unsigned)gx < 64u && (unsigned)gy < 64u && (unsigned)gz < 64u)
                offs[k] = (((gx << 6) + gy) << 6) + gz;
        }
    }

    unsigned long long acc2[4][NP];
#pragma unroll
    for (int t = 0; t < 4; ++t)
#pragma unroll
        for (int j = 0; j < NP; ++j) acc2[t][j] = 0ULL;

    const float* inb = in + (size_t)b * CI * NVOX;
    const int cobase = cog * CO_PER;

    float pv[NLOAD];
#pragma unroll
    for (int k = 0; k < NLOAD; ++k)
        pv[k] = (offs[k] >= 0) ? __ldg(inb + offs[k]) : 0.0f;
#pragma unroll
    for (int k = 0; k < NLOAD; ++k) {
        int i = tid + k * NT;
        if (i < 1000) s_tile[0][i] = pv[k];
    }

    int cur = 0;
    for (int ci = 0; ci < CI; ++ci) {
        int c = ci % WCHUNK;
        if (c == 0) {
            if (ci > 0) __syncthreads();
            int chunk = ci / WCHUNK;
            for (int i = tid; i < WELEMS; i += NT) {
                int co = i % CO; int t2 = i / CO;
                int tap = t2 % 27; int cc = t2 / 27;
                s_w[i] = W[co * (CI * 27) + (chunk * WCHUNK + cc) * 27 + tap];
            }
        }
        __syncthreads();

        if (ci + 1 < CI) {
            const float* incn = inb + (ci + 1) * NVOX;
#pragma unroll
            for (int k = 0; k < NLOAD; ++k)
                pv[k] = (offs[k] >= 0) ? __ldg(incn + offs[k]) : 0.0f;
        }

        const float* tile = s_tile[cur];
        const float* swc  = s_w + c * 27 * CO;
#pragma unroll
        for (int dx = 0; dx < 3; ++dx) {
#pragma unroll
            for (int dy = 0; dy < 3; ++dy) {
                const float* tp = tile + ((x + dx) * 10 + (y + dy)) * 10 + z0;
                float2 p0 = *reinterpret_cast<const float2*>(tp + 0);
                float2 p1 = *reinterpret_cast<const float2*>(tp + 2);
                float2 p2 = *reinterpret_cast<const float2*>(tp + 4);
                unsigned long long vb[6];
                vb[0] = bcast2(p0.x); vb[1] = bcast2(p0.y);
                vb[2] = bcast2(p1.x); vb[3] = bcast2(p1.y);
                vb[4] = bcast2(p2.x); vb[5] = bcast2(p2.y);
#pragma unroll
                for (int dz = 0; dz < 3; ++dz) {
                    int tap = (dx * 3 + dy) * 3 + dz;
                    const unsigned long long* wp =
                        reinterpret_cast<const unsigned long long*>(
                            swc + tap * CO + cobase);
                    unsigned long long wr[NP];
#pragma unroll
                    for (int j = 0; j < NP; ++j) wr[j] = wp[j];
#pragma unroll
                    for (int t = 0; t < 4; ++t)
#pragma unroll
                        for (int j = 0; j < NP; ++j)
                            ffma2(acc2[t][j], vb[t + dz], wr[j]);
                }
            }
        }

        if (ci + 1 < CI) {
#pragma unroll
            for (int k = 0; k < NLOAD; ++k) {
                int i = tid + k * NT;
                if (i < 1000) s_tile[cur ^ 1][i] = pv[k];
            }
            cur ^= 1;
        }
    }

    float a = 0.0f;
    if (PRELU) a = alpha[0];

    if (OUTMODE == 1) {
        // interleaved split bf16 out: g_s0[(b*NVOX+sp)*64 + co] (hi), +32 (lo)
#pragma unroll
        for (int t = 0; t < 4; ++t) {
            __align__(16) __nv_bfloat16 hv[CO_PER], lv[CO_PER];
#pragma unroll
            for (int j = 0; j < NP; ++j) {
                int co0 = cobase + 2 * j;
                float lo, hi;
                unpack2(acc2[t][j], lo, hi);
                lo += bias[co0]; hi += bias[co0 + 1];
                if (PRELU) {
                    lo = (lo >= 0.0f) ? lo : a * lo;
                    hi = (hi >= 0.0f) ? hi : a * hi;
                }
                __nv_bfloat16 h0 = __float2bfloat16(lo);
                __nv_bfloat16 h1 = __float2bfloat16(hi);
                hv[2*j]   = h0; lv[2*j]   = __float2bfloat16(lo - __bfloat162float(h0));
                hv[2*j+1] = h1; lv[2*j+1] = __float2bfloat16(hi - __bfloat162float(h1));
            }
            size_t sp = ((((size_t)(ox + x) << 6) + (oy + y)) << 6) + oz + z0 + t;
            size_t o = ((size_t)b * NVOX + sp) * 64 + cobase;
            *reinterpret_cast<uint4*>(g_s0 + o)      = *reinterpret_cast<uint4*>(hv);
            *reinterpret_cast<uint4*>(g_s0 + o + 32) = *reinterpret_cast<uint4*>(lv);
        }
    } else {
#pragma unroll
        for (int j = 0; j < NP; ++j) {
            int co0 = cobase + 2 * j;
            float bb0 = bias[co0], bb1 = bias[co0 + 1];
            float r0[4], r1[4];
#pragma unroll
            for (int t = 0; t < 4; ++t) {
                float lo, hi;
                unpack2(acc2[t][j], lo, hi);
                lo += bb0; hi += bb1;
                if (PRELU) {
                    lo = (lo >= 0.0f) ? lo : a * lo;
                    hi = (hi >= 0.0f) ? hi : a * hi;
                }
                r0[t] = lo; r1[t] = hi;
            }
            size_t sp = ((((size_t)(ox + x) << 6) + (oy + y)) << 6) + oz + z0;
            size_t o0 = (size_t)(b * CO + co0) * NVOX + sp;
            *reinterpret_cast<float4*>(out + o0) =
                make_float4(r0[0], r0[1], r0[2], r0[3]);
            *reinterpret_cast<float4*>(out + o0 + NVOX) =
                make_float4(r1[0], r1[1], r1[2], r1[3]);
        }
    }
}

// ---------------------------------------------------------------------------
// Weight prep: split fp32 W[co][ci][27] into bf16 hi/lo [tap][co][hi32|lo32]
// ---------------------------------------------------------------------------
__global__ void wprep_kernel(const float* __restrict__ W, int sel) {
    __nv_bfloat16* wp = (sel == 1) ? g_w1p : g_w2p;
    int i = blockIdx.x * blockDim.x + threadIdx.x;
    if (i >= 27 * 32 * 32) return;
    int tap = i >> 10, r = i & 1023, co = r >> 5, ci = r & 31;
    float w = W[co * (32 * 27) + ci * 27 + tap];
    __nv_bfloat16 h = __float2bfloat16(w);
    wp[(tap * 32 + co) * 64 + ci] = h;
    wp[(tap * 32 + co) * 64 + 32 + ci] = __float2bfloat16(w - __bfloat162float(h));
}

// ---------------------------------------------------------------------------
// mma.sync bf16-split implicit-GEMM conv 32->32 + PReLU (R14 shape).
// Block: 256 thr (8 warps). Tile: x fixed, 4y x 64z = M=256 rows, N=32 co.
// A region (3x * 6y * 64z voxels, 128B [hi|lo]) staged once = 144 KB smem.
// W staged in 9-TAP GROUPS (one dx-plane each), double-buffered 2x36KB:
// only 3 mid-loop barriers per block (vs 27 per-tap barriers in R14).
// Warp w: rows m = w*32..w*32+31 (2 m16 tiles).
// Lo-half ldmatrix addresses use SWZ(o+64) — NOT SWZ(o)+64 (carry corrupts).
// ---------------------------------------------------------------------------
#define A_BYTES (1152 * 128)                   // 147456
#define W_OFF   A_BYTES
#define WG_BYTES (9 * 4096)                    // 36864 per tap-group
#define Z_OFF   (A_BYTES + 2 * WG_BYTES)       // zero rows (256B)
#define TC_SMEM (A_BYTES + 2 * WG_BYTES + 256) // 221440

template <int LAYER>
__global__ void __launch_bounds__(256, 1)
tconv_kernel(const float* __restrict__ bias, const float* __restrict__ alpha) {
    const __nv_bfloat16* in = (LAYER == 1) ? g_s0 : g_s1;
    const __nv_bfloat16* wp = (LAYER == 1) ? g_w1p : g_w2p;

    extern __shared__ __align__(1024) char smem[];
    uint32_t sb = smem_u32(smem);

    int tid = threadIdx.x, lane = tid & 31, w = tid >> 5;
    int bidx = blockIdx.x;
    int x = bidx & 63, yg = (bidx >> 6) & 15, b = bidx >> 10;
    int oy = yg << 2;

    // per-thread W staging coords (one tap = 32 rows x 8 chunks = 256 thr)
    int wrow = tid >> 3, wch = tid & 7;
    uint32_t wsts = SWZ((uint32_t)(wrow * 128 + wch * 16));

    // ---- stage A region: voxel u = (xi*6 + yi)*64 + zi, 8 chunks of 16B ----
    {
        const __nv_bfloat16* inb = in + (size_t)b * NVOX * 64;
#pragma unroll 4
        for (int i = tid; i < 1152 * 8; i += 256) {
            int u = i >> 3, ch = i & 7;
            int xi = u / 384, rem = u - xi * 384;
            int yi = rem >> 6, zi = rem & 63;
            int gx = x + xi - 1, gy = oy + yi - 1;
            uint4 v = make_uint4(0, 0, 0, 0);
            if ((unsigned)gx < 64u && (unsigned)gy < 64u)
                v = *reinterpret_cast<const uint4*>(
                    inb + ((((size_t)(gx << 6) + gy) << 6) + zi) * 64 + ch * 8);
            uint32_t d = sb + SWZ((uint32_t)(u * 128 + ch * 16));
            asm volatile("st.shared.v4.b32 [%0], {%1,%2,%3,%4};"
                         :: "r"(d), "r"(v.x), "r"(v.y), "r"(v.z), "r"(v.w)
                         : "memory");
        }
    }
    // ---- stage W group 0 (taps 0..8) into buf 0 ----
    {
#pragma unroll
        for (int j = 0; j < 9; ++j) {
            uint4 v = *reinterpret_cast<const uint4*>(
                wp + (size_t)(j * 32 + wrow) * 64 + wch * 8);
            uint32_t d = sb + W_OFF + (uint32_t)(j * 4096) + wsts;
            asm volatile("st.shared.v4.b32 [%0], {%1,%2,%3,%4};"
                         :: "r"(d), "r"(v.x), "r"(v.y), "r"(v.z), "r"(v.w)
                         : "memory");
        }
    }
    if (tid < 16) {
        uint32_t d = sb + Z_OFF + tid * 16;
        asm volatile("st.shared.v4.b32 [%0], {%1,%1,%1,%1};"
                     :: "r"(d), "r"(0u) : "memory");
    }
    __syncthreads();

    // ---- per-lane invariants ----
    int r15 = lane & 15, kc = lane >> 4;
    uint32_t laneA[2]; int zm1v[2];
#pragma unroll
    for (int mt = 0; mt < 2; ++mt) {
        int m = w * 32 + mt * 16 + r15;
        int yb = m >> 6, z = m & 63;
        laneA[mt] = (uint32_t)(yb * 8192);
        zm1v[mt] = z - 1;
    }
    // W ldmatrix lane bases (hi and lo swizzled separately)
    int wco = (lane & 7) + ((lane >> 4) << 3);
    int cadd = (lane >> 3) & 1;
    uint32_t wbh[2][2], wbl[2][2];
#pragma unroll
    for (int ks = 0; ks < 2; ++ks)
#pragma unroll
        for (int h = 0; h < 2; ++h) {
            int co = wco + h * 16;
            uint32_t o = (uint32_t)(co * 128 + (ks * 2 + cadd) * 16);
            wbh[ks][h] = SWZ(o);
            wbl[ks][h] = SWZ(o + 64);
        }

    float acc[2][4][4];
#pragma unroll
    for (int mt = 0; mt < 2; ++mt)
#pragma unroll
        for (int nt = 0; nt < 4; ++nt)
#pragma unroll
            for (int q = 0; q < 4; ++q) acc[mt][nt][q] = 0.0f;

    // ---- group loop: g = dx plane; 9 barrier-free taps per group ----
    for (int g = 0; g < 3; ++g) {
        // prefetch next group's W (9 uint4/thread; hides under 9 taps of mma)
        uint4 pv[9];
        if (g < 2) {
#pragma unroll
            for (int j = 0; j < 9; ++j)
                pv[j] = *reinterpret_cast<const uint4*>(
                    wp + (size_t)(((g + 1) * 9 + j) * 32 + wrow) * 64 + wch * 8);
        }

        uint32_t wgbuf = sb + W_OFF + (uint32_t)((g & 1) * WG_BYTES);
        uint32_t tapx = (uint32_t)(g * 49152);   // dx plane offset in A

        for (int t9 = 0; t9 < 9; ++t9) {
            int dz = t9 % 3, dy = t9 / 3;
            uint32_t tapoff = tapx + (uint32_t)(dy * 8192);

            // A fragments (hi at SWZ(o), lo at SWZ(o+64))
            uint32_t ahf[2][2][4], alf[2][2][4];
#pragma unroll
            for (int mt = 0; mt < 2; ++mt) {
                int zs = zm1v[mt] + dz;
                bool ok = (unsigned)zs < 64u;
                uint32_t vox = tapoff + laneA[mt] + (uint32_t)(zs * 128);
#pragma unroll
                for (int ks = 0; ks < 2; ++ks) {
                    uint32_t o  = vox + (uint32_t)((ks * 2 + kc) * 16);
                    uint32_t ah = ok ? sb + SWZ(o)      : sb + Z_OFF;
                    uint32_t al = ok ? sb + SWZ(o + 64) : sb + Z_OFF + 64;
                    ldsm4(ahf[mt][ks], ah);
                    ldsm4(alf[mt][ks], al);
                }
            }
            // W fragments from resident group buffer
            uint32_t whf[2][8], wlf[2][8];
            {
                uint32_t wbuf = wgbuf + (uint32_t)(t9 * 4096);
#pragma unroll
                for (int ks = 0; ks < 2; ++ks)
#pragma unroll
                    for (int h = 0; h < 2; ++h) {
                        ldsm4(&whf[ks][h * 4], wbuf + wbh[ks][h]);
                        ldsm4(&wlf[ks][h * 4], wbuf + wbl[ks][h]);
                    }
            }
            // mma: Ah*Wh + Al*Wh + Ah*Wl
#pragma unroll
            for (int mt = 0; mt < 2; ++mt)
#pragma unroll
                for (int nt = 0; nt < 4; ++nt) {
                    float* d = acc[mt][nt];
#pragma unroll
                    for (int ks = 0; ks < 2; ++ks) {
                        mma16816(d, ahf[mt][ks], &whf[ks][nt * 2]);
                        mma16816(d, alf[mt][ks], &whf[ks][nt * 2]);
                        mma16816(d, ahf[mt][ks], &wlf[ks][nt * 2]);
                    }
                }
        }

        // store prefetched group and sync (3 barriers total in this loop)
        if (g < 2) {
            uint32_t dstb = sb + W_OFF + (uint32_t)(((g + 1) & 1) * WG_BYTES);
#pragma unroll
            for (int j = 0; j < 9; ++j) {
                uint32_t d = dstb + (uint32_t)(j * 4096) + wsts;
                asm volatile("st.shared.v4.b32 [%0], {%1,%2,%3,%4};"
                             :: "r"(d), "r"(pv[j].x), "r"(pv[j].y),
                                "r"(pv[j].z), "r"(pv[j].w) : "memory");
            }
            __syncthreads();
        }
    }

    // ---- epilogue: bias + PReLU; LAYER 1 -> split bf16 g_s1, LAYER 2 -> f32
    float a = alpha[0];
#pragma unroll
    for (int mt = 0; mt < 2; ++mt) {
#pragma unroll
        for (int rr = 0; rr < 2; ++rr) {
            int m = w * 32 + mt * 16 + (lane >> 2) + rr * 8;
            int yb = m >> 6, z = m & 63;
            size_t sp = (((size_t)(x << 6) + (oy + yb)) << 6) + z;
#pragma unroll
            for (int nt = 0; nt < 4; ++nt) {
                int c = nt * 8 + (lane & 3) * 2;
                float v0 = acc[mt][nt][rr * 2 + 0] + __ldg(bias + c);
                float v1 = acc[mt][nt][rr * 2 + 1] + __ldg(bias + c + 1);
                v0 = (v0 >= 0.0f) ? v0 : a * v0;
                v1 = (v1 >= 0.0f) ? v1 : a * v1;
                if (LAYER == 1) {
                    __nv_bfloat16 h0 = __float2bfloat16(v0);
                    __nv_bfloat16 h1 = __float2bfloat16(v1);
                    __nv_bfloat16 l0 = __float2bfloat16(v0 - __bfloat162float(h0));
                    __nv_bfloat16 l1 = __float2bfloat16(v1 - __bfloat162float(h1));
                    size_t o = ((size_t)b * NVOX + sp) * 64 + c;
                    *reinterpret_cast<uint32_t*>(g_s1 + o)      = packbf(h0, h1);
                    *reinterpret_cast<uint32_t*>(g_s1 + o + 32) = packbf(l0, l1);
                } else {
                    g_bufA[((size_t)(b * 32 + c))     * NVOX + sp] = v0;
                    g_bufA[((size_t)(b * 32 + c + 1)) * NVOX + sp] = v1;
                }
            }
        }
    }
}

// ---------------------------------------------------------------------------
__global__ void gather_kernel(const float* __restrict__ locs,
                              float* __restrict__ out) {
    int p = blockIdx.x * blockDim.x + threadIdx.x;
    if (p >= BATCH * NPART) return;
    int b = p / NPART;
    const float* g = g_out4 + (size_t)b * COUTC * NVOX;
    float px = locs[3*p+0] * 64.0f - 0.5f;
    float py = locs[3*p+1] * 64.0f - 0.5f;
    float pz = locs[3*p+2] * 64.0f - 0.5f;
    int ix = (int)floorf(px), iy = (int)floorf(py), iz = (int)floorf(pz);
    float fx = px - (float)ix, fy = py - (float)iy, fz = pz - (float)iz;
    float r0 = 0.f, r1 = 0.f, r2 = 0.f, r3 = 0.f;
#pragma unroll
    for (int dx = 0; dx < 2; ++dx) {
        int jx = ix + dx;
        float wx = dx ? fx : 1.0f - fx;
#pragma unroll
        for (int dy = 0; dy < 2; ++dy) {
            int jy = iy + dy;
            float wxy = wx * (dy ? fy : 1.0f - fy);
#pragma unroll
            for (int dz = 0; dz < 2; ++dz) {
                int jz = iz + dz;
                float w = wxy * (dz ? fz : 1.0f - fz);
                if ((unsigned)jx < 64u && (unsigned)jy < 64u && (unsigned)jz < 64u) {
                    int flat = ((jx << 6) + jy) * 64 + jz;
                    r0 += w * g[0*NVOX + flat];
                    r1 += w * g[1*NVOX + flat];
                    r2 += w * g[2*NVOX + flat];
                    r3 += w * g[3*NVOX + flat];
                }
            }
        }
    }
    out[4*p+0] = r0; out[4*p+1] = r1; out[4*p+2] = r2; out[4*p+3] = r3;
}

// ---------------------------------------------------------------------------
extern "C" void kernel_launch(void* const* d_in, const int* in_sizes, int n_in,
                              void* d_out, int out_size) {
    const float* locs = (const float*)d_in[0];
    const float* data = (const float*)d_in[1];
    const float* dens = (const float*)d_in[2];
    const float* W0 = (const float*)d_in[3];
    const float* b0 = (const float*)d_in[4];
    const float* W1 = (const float*)d_in[5];
    const float* b1 = (const float*)d_in[6];
    const float* W2 = (const float*)d_in[7];
    const float* b2 = (const float*)d_in[8];
    const float* W3 = (const float*)d_in[9];
    const float* b3 = (const float*)d_in[10];
    const float* a0 = (const float*)d_in[11];
    const float* a1 = (const float*)d_in[12];
    const float* a2 = (const float*)d_in[13];
    float* out = (float*)d_out;
    (void)in_sizes; (void)n_in; (void)out_size;

    cudaFuncSetAttribute(tconv_kernel<1>,
                         cudaFuncAttributeMaxDynamicSharedMemorySize, TC_SMEM);
    cudaFuncSetAttribute(tconv_kernel<2>,
                         cudaFuncAttributeMaxDynamicSharedMemorySize, TC_SMEM);

    zero_grid0_kernel<<<512, 256>>>();
    splat_kernel<<<(BATCH * NPART + 127) / 128, 128>>>(locs, data, dens);

    wprep_kernel<<<108, 256>>>(W1, 1);
    wprep_kernel<<<108, 256>>>(W2, 2);

    // layer0: FFMA2 conv -> split bf16 g_s0
    conv3d_kernel<CIN, CMID, 8, true, 1><<<1024, 512>>>(0, 1, W0, b0, a0);
    // layers 1,2: mma.sync bf16-split implicit GEMM (grouped W, 3 barriers)
    tconv_kernel<1><<<2048, 256, TC_SMEM>>>(b1, a1);
    tconv_kernel<2><<<2048, 256, TC_SMEM>>>(b2, a2);
    // layer3: FFMA2 conv, g_bufA -> g_out4
    conv3d_kernel<CMID, COUTC, 2, false, 0><<<1024, 256>>>(1, 2, W3, b3, a0);

    gather_kernel<<<(BATCH * NPART + 127) / 128, 128>>>(locs, out);
}

// round 17
// speedup vs baseline: 1.2001x; 1.0371x over previous
#include <cuda_runtime.h>
#include <cuda_bf16.h>
#include <math.h>
#include <stdint.h>

#define NVOX   (64*64*64)
#define BATCH  2
#define NPART  32768
#define CIN    4
#define CMID   32
#define COUTC  4

// ---------------- device global scratch (no allocation allowed) ------------
__device__ float g_grid0[BATCH*CIN *NVOX];   // splat out [B,4,64,64,64] NCDHW
__device__ float g_bufA [BATCH*CMID*NVOX];   // layer2 f32 NCDHW out -> layer3 in
__device__ float g_out4 [BATCH*COUTC*NVOX];  // layer3 out

// split bf16 activations, layout [b][x][y][z][hi(32)|lo(32)] (128B per voxel)
__device__ __nv_bfloat16 g_s0[(size_t)BATCH*NVOX*64];
__device__ __nv_bfloat16 g_s1[(size_t)BATCH*NVOX*64];
// pre-split weights, layout [tap(27)][co(32)][hi 32 | lo 32] bf16 (128B per co)
__device__ __nv_bfloat16 g_w1p[27*32*64];
__device__ __nv_bfloat16 g_w2p[27*32*64];

__device__ __forceinline__ float* buf_ptr(int s) {
    switch (s) { case 0: return g_grid0; case 1: return g_bufA;
                 default: return g_out4; }
}

// ---------------- packed fp32x2 helpers ------------------------------------
__device__ __forceinline__ unsigned long long bcast2(float v) {
    unsigned long long r; unsigned int b = __float_as_uint(v);
    asm("mov.b64 %0, {%1, %1};" : "=l"(r) : "r"(b));
    return r;
}
__device__ __forceinline__ void ffma2(unsigned long long& acc,
                                      unsigned long long a, unsigned long long b) {
    asm("fma.rn.f32x2 %0, %1, %2, %0;" : "+l"(acc) : "l"(a), "l"(b));
}
__device__ __forceinline__ void unpack2(unsigned long long v, float& lo, float& hi) {
    unsigned int l, h;
    asm("mov.b64 {%0, %1}, %2;" : "=r"(l), "=r"(h) : "l"(v));
    lo = __uint_as_float(l); hi = __uint_as_float(h);
}

// ---------------- mma.sync / ldmatrix helpers (sm_80+, OK on sm_103) -------
__device__ __forceinline__ uint32_t smem_u32(const void* p) {
    uint32_t a;
    asm("{ .reg .u64 t; cvta.to.shared.u64 t, %1; cvt.u32.u64 %0, t; }"
        : "=r"(a) : "l"(p));
    return a;
}
__device__ __forceinline__ void ldsm4(uint32_t* r, uint32_t a) {
    asm volatile("ldmatrix.sync.aligned.m8n8.x4.shared.b16 {%0,%1,%2,%3}, [%4];"
        : "=r"(r[0]), "=r"(r[1]), "=r"(r[2]), "=r"(r[3]) : "r"(a));
}
__device__ __forceinline__ void mma16816(float* d, const uint32_t* a,
                                         const uint32_t* b) {
    asm volatile("mma.sync.aligned.m16n8k16.row.col.f32.bf16.bf16.f32 "
        "{%0,%1,%2,%3}, {%4,%5,%6,%7}, {%8,%9}, {%0,%1,%2,%3};"
        : "+f"(d[0]), "+f"(d[1]), "+f"(d[2]), "+f"(d[3])
        : "r"(a[0]), "r"(a[1]), "r"(a[2]), "r"(a[3]), "r"(b[0]), "r"(b[1]));
}
#define SWZ(o) ((o) ^ (((o) >> 3) & 0x70))

__device__ __forceinline__ uint32_t packbf(__nv_bfloat16 a, __nv_bfloat16 b) {
    unsigned short ua = *reinterpret_cast<unsigned short*>(&a);
    unsigned short ub = *reinterpret_cast<unsigned short*>(&b);
    return (uint32_t)ua | ((uint32_t)ub << 16);
}

// ---------------------------------------------------------------------------
__global__ void zero_grid0_kernel() {
    int n = BATCH * CIN * NVOX;
    for (int i = blockIdx.x * blockDim.x + threadIdx.x; i < n;
         i += gridDim.x * blockDim.x)
        g_grid0[i] = 0.0f;
}

// ---------------------------------------------------------------------------
__global__ void splat_kernel(const float* __restrict__ locs,
                             const float* __restrict__ data,
                             const float* __restrict__ dens) {
    int p = blockIdx.x * blockDim.x + threadIdx.x;
    if (p >= BATCH * NPART) return;
    int b = p / NPART;
    float lx = locs[3*p+0], ly = locs[3*p+1], lz = locs[3*p+2];
    float inv = 1.0f / dens[p];
    float d0 = data[4*p+0]*inv, d1 = data[4*p+1]*inv;
    float d2c = data[4*p+2]*inv, d3 = data[4*p+3]*inv;
    const float STEP = 0.015625f, INVSTEP = 64.0f, H2 = 0.0009765625f;
    const float C6 = (float)(315.0 / (64.0 * 3.14159265358979323846 *
                                      2.8421709430404007e-14));
    int bx = (int)floorf(lx * INVSTEP);
    int by = (int)floorf(ly * INVSTEP);
    int bz = (int)floorf(lz * INVSTEP);
    float* gb = g_grid0 + (size_t)b * CIN * NVOX;
    for (int ox = -2; ox <= 2; ++ox) {
        int cx = bx + ox; if ((unsigned)cx >= 64u) continue;
        float ddx = ((float)cx + 0.5f) * STEP - lx;
        float sx = ddx * ddx;
        for (int oy = -2; oy <= 2; ++oy) {
            int cy = by + oy; if ((unsigned)cy >= 64u) continue;
            float ddy = ((float)cy + 0.5f) * STEP - ly;
            float sxy = sx + ddy * ddy;
            if (sxy > H2) continue;
            for (int oz = -2; oz <= 2; ++oz) {
                int cz = bz + oz; if ((unsigned)cz >= 64u) continue;
                float ddz = ((float)cz + 0.5f) * STEP - lz;
                float dd2 = sxy + ddz * ddz;
                if (dd2 > H2) continue;
                float t = H2 - dd2;
                float w = C6 * t * t * t;
                int flat = ((cx << 6) + cy) * 64 + cz;
                atomicAdd(gb + 0*NVOX + flat, w * d0);
                atomicAdd(gb + 1*NVOX + flat, w * d1);
                atomicAdd(gb + 2*NVOX + flat, w * d2c);
                atomicAdd(gb + 3*NVOX + flat, w * d3);
            }
        }
    }
}

// ---------------------------------------------------------------------------
// FFMA2 direct conv (R8 proven). OUTMODE: 0 = f32 NCDHW, 1 = split bf16.
// ---------------------------------------------------------------------------
template <int CI, int CO, int CO_PER, bool PRELU, int OUTMODE>
__global__ void __launch_bounds__(128 * (CO / CO_PER), 2)
conv3d_kernel(int in_sel, int out_sel,
              const float* __restrict__ W,
              const float* __restrict__ bias,
              const float* __restrict__ alpha) {
    constexpr int NP     = CO_PER / 2;
    constexpr int NT     = 128 * (CO / CO_PER);
    constexpr int WCHUNK = (CI < 16) ? CI : 16;
    constexpr int WELEMS = WCHUNK * 27 * CO;
    constexpr int NLOAD  = (1000 + NT - 1) / NT;

    const float* in  = buf_ptr(in_sel);
    float*       out = buf_ptr(out_sel);

    int tid = threadIdx.x;
    int x = tid & 7, y = (tid >> 3) & 7, zg = (tid >> 6) & 1, cog = tid >> 7;
    int bidx = blockIdx.x;
    int tz = bidx & 7, ty = (bidx >> 3) & 7, tx = (bidx >> 6) & 7;
    int b  = bidx >> 9;
    int ox = tx << 3, oy = ty << 3, oz = tz << 3;
    int z0 = zg << 2;

    __shared__ __align__(16) float s_tile[2][1000];
    __shared__ __align__(16) float s_w[WELEMS];

    int offs[NLOAD];
#pragma unroll
    for (int k = 0; k < NLOAD; ++k) {
        int i = tid + k * NT;
        offs[k] = -1;
        if (i < 1000) {
            int lz = i % 10; int r = i / 10; int ly = r % 10; int lx = r / 10;
            int gx = ox + lx - 1, gy = oy + ly - 1, gz = oz + lz - 1;
            if ((unsigned)gx < 64u && (unsigned)gy < 64u && (unsigned)gz < 64u)
                offs[k] = (((gx << 6) + gy) << 6) + gz;
        }
    }

    unsigned long long acc2[4][NP];
#pragma unroll
    for (int t = 0; t < 4; ++t)
#pragma unroll
        for (int j = 0; j < NP; ++j) acc2[t][j] = 0ULL;

    const float* inb = in + (size_t)b * CI * NVOX;
    const int cobase = cog * CO_PER;

    float pv[NLOAD];
#pragma unroll
    for (int k = 0; k < NLOAD; ++k)
        pv[k] = (offs[k] >= 0) ? __ldg(inb + offs[k]) : 0.0f;
#pragma unroll
    for (int k = 0; k < NLOAD; ++k) {
        int i = tid + k * NT;
        if (i < 1000) s_tile[0][i] = pv[k];
    }

    int cur = 0;
    for (int ci = 0; ci < CI; ++ci) {
        int c = ci % WCHUNK;
        if (c == 0) {
            if (ci > 0) __syncthreads();
            int chunk = ci / WCHUNK;
            for (int i = tid; i < WELEMS; i += NT) {
                int co = i % CO; int t2 = i / CO;
                int tap = t2 % 27; int cc = t2 / 27;
                s_w[i] = W[co * (CI * 27) + (chunk * WCHUNK + cc) * 27 + tap];
            }
        }
        __syncthreads();

        if (ci + 1 < CI) {
            const float* incn = inb + (ci + 1) * NVOX;
#pragma unroll
            for (int k = 0; k < NLOAD; ++k)
                pv[k] = (offs[k] >= 0) ? __ldg(incn + offs[k]) : 0.0f;
        }

        const float* tile = s_tile[cur];
        const float* swc  = s_w + c * 27 * CO;
#pragma unroll
        for (int dx = 0; dx < 3; ++dx) {
#pragma unroll
            for (int dy = 0; dy < 3; ++dy) {
                const float* tp = tile + ((x + dx) * 10 + (y + dy)) * 10 + z0;
                float2 p0 = *reinterpret_cast<const float2*>(tp + 0);
                float2 p1 = *reinterpret_cast<const float2*>(tp + 2);
                float2 p2 = *reinterpret_cast<const float2*>(tp + 4);
                unsigned long long vb[6];
                vb[0] = bcast2(p0.x); vb[1] = bcast2(p0.y);
                vb[2] = bcast2(p1.x); vb[3] = bcast2(p1.y);
                vb[4] = bcast2(p2.x); vb[5] = bcast2(p2.y);
#pragma unroll
                for (int dz = 0; dz < 3; ++dz) {
                    int tap = (dx * 3 + dy) * 3 + dz;
                    const unsigned long long* wp =
                        reinterpret_cast<const unsigned long long*>(
                            swc + tap * CO + cobase);
                    unsigned long long wr[NP];
#pragma unroll
                    for (int j = 0; j < NP; ++j) wr[j] = wp[j];
#pragma unroll
                    for (int t = 0; t < 4; ++t)
#pragma unroll
                        for (int j = 0; j < NP; ++j)
                            ffma2(acc2[t][j], vb[t + dz], wr[j]);
                }
            }
        }

        if (ci + 1 < CI) {
#pragma unroll
            for (int k = 0; k < NLOAD; ++k) {
                int i = tid + k * NT;
                if (i < 1000) s_tile[cur ^ 1][i] = pv[k];
            }
            cur ^= 1;
        }
    }

    float a = 0.0f;
    if (PRELU) a = alpha[0];

    if (OUTMODE == 1) {
        // interleaved split bf16 out: g_s0[(b*NVOX+sp)*64 + co] (hi), +32 (lo)
#pragma unroll
        for (int t = 0; t < 4; ++t) {
            __align__(16) __nv_bfloat16 hv[CO_PER], lv[CO_PER];
#pragma unroll
            for (int j = 0; j < NP; ++j) {
                int co0 = cobase + 2 * j;
                float lo, hi;
                unpack2(acc2[t][j], lo, hi);
                lo += bias[co0]; hi += bias[co0 + 1];
                if (PRELU) {
                    lo = (lo >= 0.0f) ? lo : a * lo;
                    hi = (hi >= 0.0f) ? hi : a * hi;
                }
                __nv_bfloat16 h0 = __float2bfloat16(lo);
                __nv_bfloat16 h1 = __float2bfloat16(hi);
                hv[2*j]   = h0; lv[2*j]   = __float2bfloat16(lo - __bfloat162float(h0));
                hv[2*j+1] = h1; lv[2*j+1] = __float2bfloat16(hi - __bfloat162float(h1));
            }
            size_t sp = ((((size_t)(ox + x) << 6) + (oy + y)) << 6) + oz + z0 + t;
            size_t o = ((size_t)b * NVOX + sp) * 64 + cobase;
            *reinterpret_cast<uint4*>(g_s0 + o)      = *reinterpret_cast<uint4*>(hv);
            *reinterpret_cast<uint4*>(g_s0 + o + 32) = *reinterpret_cast<uint4*>(lv);
        }
    } else {
#pragma unroll
        for (int j = 0; j < NP; ++j) {
            int co0 = cobase + 2 * j;
            float bb0 = bias[co0], bb1 = bias[co0 + 1];
            float r0[4], r1[4];
#pragma unroll
            for (int t = 0; t < 4; ++t) {
                float lo, hi;
                unpack2(acc2[t][j], lo, hi);
                lo += bb0; hi += bb1;
                if (PRELU) {
                    lo = (lo >= 0.0f) ? lo : a * lo;
                    hi = (hi >= 0.0f) ? hi : a * hi;
                }
                r0[t] = lo; r1[t] = hi;
            }
            size_t sp = ((((size_t)(ox + x) << 6) + (oy + y)) << 6) + oz + z0;
            size_t o0 = (size_t)(b * CO + co0) * NVOX + sp;
            *reinterpret_cast<float4*>(out + o0) =
                make_float4(r0[0], r0[1], r0[2], r0[3]);
            *reinterpret_cast<float4*>(out + o0 + NVOX) =
                make_float4(r1[0], r1[1], r1[2], r1[3]);
        }
    }
}

// ---------------------------------------------------------------------------
// Weight prep: split fp32 W[co][ci][27] into bf16 hi/lo [tap][co][hi32|lo32]
// ---------------------------------------------------------------------------
__global__ void wprep_kernel(const float* __restrict__ W, int sel) {
    __nv_bfloat16* wp = (sel == 1) ? g_w1p : g_w2p;
    int i = blockIdx.x * blockDim.x + threadIdx.x;
    if (i >= 27 * 32 * 32) return;
    int tap = i >> 10, r = i & 1023, co = r >> 5, ci = r & 31;
    float w = W[co * (32 * 27) + ci * 27 + tap];
    __nv_bfloat16 h = __float2bfloat16(w);
    wp[(tap * 32 + co) * 64 + ci] = h;
    wp[(tap * 32 + co) * 64 + 32 + ci] = __float2bfloat16(w - __bfloat162float(h));
}

// ---------------------------------------------------------------------------
// mma.sync bf16-split implicit-GEMM conv 32->32 + PReLU (R16 + unrolled taps).
// Block: 256 thr (8 warps). Tile: x fixed, 4y x 64z = M=256 rows, N=32 co.
// A region (3x * 6y * 64z voxels, 128B [hi|lo]) staged once = 144 KB smem.
// W staged in 9-TAP GROUPS (one dx-plane each), double-buffered 2x36KB.
// The 9-tap loop is FULLY UNROLLED so ptxas software-pipelines LDSM under MMA.
// Warp w: rows m = w*32..w*32+31 (2 m16 tiles).
// Lo-half ldmatrix addresses use SWZ(o+64) — NOT SWZ(o)+64 (carry corrupts).
// ---------------------------------------------------------------------------
#define A_BYTES (1152 * 128)                   // 147456
#define W_OFF   A_BYTES
#define WG_BYTES (9 * 4096)                    // 36864 per tap-group
#define Z_OFF   (A_BYTES + 2 * WG_BYTES)       // zero rows (256B)
#define TC_SMEM (A_BYTES + 2 * WG_BYTES + 256) // 221440

template <int LAYER>
__global__ void __launch_bounds__(256, 1)
tconv_kernel(const float* __restrict__ bias, const float* __restrict__ alpha) {
    const __nv_bfloat16* in = (LAYER == 1) ? g_s0 : g_s1;
    const __nv_bfloat16* wp = (LAYER == 1) ? g_w1p : g_w2p;

    extern __shared__ __align__(1024) char smem[];
    uint32_t sb = smem_u32(smem);

    int tid = threadIdx.x, lane = tid & 31, w = tid >> 5;
    int bidx = blockIdx.x;
    int x = bidx & 63, yg = (bidx >> 6) & 15, b = bidx >> 10;
    int oy = yg << 2;

    // per-thread W staging coords (one tap = 32 rows x 8 chunks = 256 thr)
    int wrow = tid >> 3, wch = tid & 7;
    uint32_t wsts = SWZ((uint32_t)(wrow * 128 + wch * 16));

    // ---- stage A region: voxel u = (xi*6 + yi)*64 + zi, 8 chunks of 16B ----
    {
        const __nv_bfloat16* inb = in + (size_t)b * NVOX * 64;
#pragma unroll 4
        for (int i = tid; i < 1152 * 8; i += 256) {
            int u = i >> 3, ch = i & 7;
            int xi = u / 384, rem = u - xi * 384;
            int yi = rem >> 6, zi = rem & 63;
            int gx = x + xi - 1, gy = oy + yi - 1;
            uint4 v = make_uint4(0, 0, 0, 0);
            if ((unsigned)gx < 64u && (unsigned)gy < 64u)
                v = *reinterpret_cast<const uint4*>(
                    inb + ((((size_t)(gx << 6) + gy) << 6) + zi) * 64 + ch * 8);
            uint32_t d = sb + SWZ((uint32_t)(u * 128 + ch * 16));
            asm volatile("st.shared.v4.b32 [%0], {%1,%2,%3,%4};"
                         :: "r"(d), "r"(v.x), "r"(v.y), "r"(v.z), "r"(v.w)
                         : "memory");
        }
    }
    // ---- stage W group 0 (taps 0..8) into buf 0 ----
    {
#pragma unroll
        for (int j = 0; j < 9; ++j) {
            uint4 v = *reinterpret_cast<const uint4*>(
                wp + (size_t)(j * 32 + wrow) * 64 + wch * 8);
            uint32_t d = sb + W_OFF + (uint32_t)(j * 4096) + wsts;
            asm volatile("st.shared.v4.b32 [%0], {%1,%2,%3,%4};"
                         :: "r"(d), "r"(v.x), "r"(v.y), "r"(v.z), "r"(v.w)
                         : "memory");
        }
    }
    if (tid < 16) {
        uint32_t d = sb + Z_OFF + tid * 16;
        asm volatile("st.shared.v4.b32 [%0], {%1,%1,%1,%1};"
                     :: "r"(d), "r"(0u) : "memory");
    }
    __syncthreads();

    // ---- per-lane invariants ----
    int r15 = lane & 15, kc = lane >> 4;
    uint32_t laneA[2]; int zm1v[2];
#pragma unroll
    for (int mt = 0; mt < 2; ++mt) {
        int m = w * 32 + mt * 16 + r15;
        int yb = m >> 6, z = m & 63;
        laneA[mt] = (uint32_t)(yb * 8192);
        zm1v[mt] = z - 1;
    }
    // W ldmatrix lane bases (hi and lo swizzled separately)
    int wco = (lane & 7) + ((lane >> 4) << 3);
    int cadd = (lane >> 3) & 1;
    uint32_t wbh[2][2], wbl[2][2];
#pragma unroll
    for (int ks = 0; ks < 2; ++ks)
#pragma unroll
        for (int h = 0; h < 2; ++h) {
            int co = wco + h * 16;
            uint32_t o = (uint32_t)(co * 128 + (ks * 2 + cadd) * 16);
            wbh[ks][h] = SWZ(o);
            wbl[ks][h] = SWZ(o + 64);
        }

    float acc[2][4][4];
#pragma unroll
    for (int mt = 0; mt < 2; ++mt)
#pragma unroll
        for (int nt = 0; nt < 4; ++nt)
#pragma unroll
            for (int q = 0; q < 4; ++q) acc[mt][nt][q] = 0.0f;

    // ---- group loop: g = dx plane; 9 FULLY-UNROLLED barrier-free taps ----
    for (int g = 0; g < 3; ++g) {
        // prefetch next group's W (9 uint4/thread; hides under 9 taps of mma)
        uint4 pv[9];
        if (g < 2) {
#pragma unroll
            for (int j = 0; j < 9; ++j)
                pv[j] = *reinterpret_cast<const uint4*>(
                    wp + (size_t)(((g + 1) * 9 + j) * 32 + wrow) * 64 + wch * 8);
        }

        uint32_t wgbuf = sb + W_OFF + (uint32_t)((g & 1) * WG_BYTES);
        uint32_t tapx = (uint32_t)(g * 49152);   // dx plane offset in A

#pragma unroll
        for (int t9 = 0; t9 < 9; ++t9) {
            const int dz = t9 % 3, dy = t9 / 3;
            uint32_t tapoff = tapx + (uint32_t)(dy * 8192);

            // A fragments (hi at SWZ(o), lo at SWZ(o+64))
            uint32_t ahf[2][2][4], alf[2][2][4];
#pragma unroll
            for (int mt = 0; mt < 2; ++mt) {
                int zs = zm1v[mt] + dz;
                bool ok = (unsigned)zs < 64u;
                uint32_t vox = tapoff + laneA[mt] + (uint32_t)(zs * 128);
#pragma unroll
                for (int ks = 0; ks < 2; ++ks) {
                    uint32_t o  = vox + (uint32_t)((ks * 2 + kc) * 16);
                    uint32_t ah = ok ? sb + SWZ(o)      : sb + Z_OFF;
                    uint32_t al = ok ? sb + SWZ(o + 64) : sb + Z_OFF + 64;
                    ldsm4(ahf[mt][ks], ah);
                    ldsm4(alf[mt][ks], al);
                }
            }
            // W fragments from resident group buffer
            uint32_t whf[2][8], wlf[2][8];
            {
                uint32_t wbuf = wgbuf + (uint32_t)(t9 * 4096);
#pragma unroll
                for (int ks = 0; ks < 2; ++ks)
#pragma unroll
                    for (int h = 0; h < 2; ++h) {
                        ldsm4(&whf[ks][h * 4], wbuf + wbh[ks][h]);
                        ldsm4(&wlf[ks][h * 4], wbuf + wbl[ks][h]);
                    }
            }
            // mma: Ah*Wh + Al*Wh + Ah*Wl
#pragma unroll
            for (int mt = 0; mt < 2; ++mt)
#pragma unroll
                for (int nt = 0; nt < 4; ++nt) {
                    float* d = acc[mt][nt];
#pragma unroll
                    for (int ks = 0; ks < 2; ++ks) {
                        mma16816(d, ahf[mt][ks], &whf[ks][nt * 2]);
                        mma16816(d, alf[mt][ks], &whf[ks][nt * 2]);
                        mma16816(d, ahf[mt][ks], &wlf[ks][nt * 2]);
                    }
                }
        }

        // store prefetched group and sync (2 barriers total in this loop)
        if (g < 2) {
            uint32_t dstb = sb + W_OFF + (uint32_t)(((g + 1) & 1) * WG_BYTES);
#pragma unroll
            for (int j = 0; j < 9; ++j) {
                uint32_t d = dstb + (uint32_t)(j * 4096) + wsts;
                asm volatile("st.shared.v4.b32 [%0], {%1,%2,%3,%4};"
                             :: "r"(d), "r"(pv[j].x), "r"(pv[j].y),
                                "r"(pv[j].z), "r"(pv[j].w) : "memory");
            }
            __syncthreads();
        }
    }

    // ---- epilogue: bias + PReLU; LAYER 1 -> split bf16 g_s1, LAYER 2 -> f32
    float a = alpha[0];
#pragma unroll
    for (int mt = 0; mt < 2; ++mt) {
#pragma unroll
        for (int rr = 0; rr < 2; ++rr) {
            int m = w * 32 + mt * 16 + (lane >> 2) + rr * 8;
            int yb = m >> 6, z = m & 63;
            size_t sp = (((size_t)(x << 6) + (oy + yb)) << 6) + z;
#pragma unroll
            for (int nt = 0; nt < 4; ++nt) {
                int c = nt * 8 + (lane & 3) * 2;
                float v0 = acc[mt][nt][rr * 2 + 0] + __ldg(bias + c);
                float v1 = acc[mt][nt][rr * 2 + 1] + __ldg(bias + c + 1);
                v0 = (v0 >= 0.0f) ? v0 : a * v0;
                v1 = (v1 >= 0.0f) ? v1 : a * v1;
                if (LAYER == 1) {
                    __nv_bfloat16 h0 = __float2bfloat16(v0);
                    __nv_bfloat16 h1 = __float2bfloat16(v1);
                    __nv_bfloat16 l0 = __float2bfloat16(v0 - __bfloat162float(h0));
                    __nv_bfloat16 l1 = __float2bfloat16(v1 - __bfloat162float(h1));
                    size_t o = ((size_t)b * NVOX + sp) * 64 + c;
                    *reinterpret_cast<uint32_t*>(g_s1 + o)      = packbf(h0, h1);
                    *reinterpret_cast<uint32_t*>(g_s1 + o + 32) = packbf(l0, l1);
                } else {
                    g_bufA[((size_t)(b * 32 + c))     * NVOX + sp] = v0;
                    g_bufA[((size_t)(b * 32 + c + 1)) * NVOX + sp] = v1;
                }
            }
        }
    }
}

// ---------------------------------------------------------------------------
__global__ void gather_kernel(const float* __restrict__ locs,
                              float* __restrict__ out) {
    int p = blockIdx.x * blockDim.x + threadIdx.x;
    if (p >= BATCH * NPART) return;
    int b = p / NPART;
    const float* g = g_out4 + (size_t)b * COUTC * NVOX;
    float px = locs[3*p+0] * 64.0f - 0.5f;
    float py = locs[3*p+1] * 64.0f - 0.5f;
    float pz = locs[3*p+2] * 64.0f - 0.5f;
    int ix = (int)floorf(px), iy = (int)floorf(py), iz = (int)floorf(pz);
    float fx = px - (float)ix, fy = py - (float)iy, fz = pz - (float)iz;
    float r0 = 0.f, r1 = 0.f, r2 = 0.f, r3 = 0.f;
#pragma unroll
    for (int dx = 0; dx < 2; ++dx) {
        int jx = ix + dx;
        float wx = dx ? fx : 1.0f - fx;
#pragma unroll
        for (int dy = 0; dy < 2; ++dy) {
            int jy = iy + dy;
            float wxy = wx * (dy ? fy : 1.0f - fy);
#pragma unroll
            for (int dz = 0; dz < 2; ++dz) {
                int jz = iz + dz;
                float w = wxy * (dz ? fz : 1.0f - fz);
                if ((unsigned)jx < 64u && (unsigned)jy < 64u && (unsigned)jz < 64u) {
                    int flat = ((jx << 6) + jy) * 64 + jz;
                    r0 += w * g[0*NVOX + flat];
                    r1 += w * g[1*NVOX + flat];
                    r2 += w * g[2*NVOX + flat];
                    r3 += w * g[3*NVOX + flat];
                }
            }
        }
    }
    out[4*p+0] = r0; out[4*p+1] = r1; out[4*p+2] = r2; out[4*p+3] = r3;
}

// ---------------------------------------------------------------------------
extern "C" void kernel_launch(void* const* d_in, const int* in_sizes, int n_in,
                              void* d_out, int out_size) {
    const float* locs = (const float*)d_in[0];
    const float* data = (const float*)d_in[1];
    const float* dens = (const float*)d_in[2];
    const float* W0 = (const float*)d_in[3];
    const float* b0 = (const float*)d_in[4];
    const float* W1 = (const float*)d_in[5];
    const float* b1 = (const float*)d_in[6];
    const float* W2 = (const float*)d_in[7];
    const float* b2 = (const float*)d_in[8];
    const float* W3 = (const float*)d_in[9];
    const float* b3 = (const float*)d_in[10];
    const float* a0 = (const float*)d_in[11];
    const float* a1 = (const float*)d_in[12];
    const float* a2 = (const float*)d_in[13];
    float* out = (float*)d_out;
    (void)in_sizes; (void)n_in; (void)out_size;

    cudaFuncSetAttribute(tconv_kernel<1>,
                         cudaFuncAttributeMaxDynamicSharedMemorySize, TC_SMEM);
    cudaFuncSetAttribute(tconv_kernel<2>,
                         cudaFuncAttributeMaxDynamicSharedMemorySize, TC_SMEM);

    zero_grid0_kernel<<<512, 256>>>();
    splat_kernel<<<(BATCH * NPART + 127) / 128, 128>>>(locs, data, dens);

    wprep_kernel<<<108, 256>>>(W1, 1);
    wprep_kernel<<<108, 256>>>(W2, 2);

    // layer0: FFMA2 conv -> split bf16 g_s0
    conv3d_kernel<CIN, CMID, 8, true, 1><<<1024, 512>>>(0, 1, W0, b0, a0);
    // layers 1,2: mma.sync bf16-split implicit GEMM (grouped W, unrolled taps)
    tconv_kernel<1><<<2048, 256, TC_SMEM>>>(b1, a1);
    tconv_kernel<2><<<2048, 256, TC_SMEM>>>(b2, a2);
    // layer3: FFMA2 conv, g_bufA -> g_out4
    conv3d_kernel<CMID, COUTC, 2, false, 0><<<1024, 256>>>(1, 2, W3, b3, a0);

    gather_kernel<<<(BATCH * NPART + 127) / 128, 128>>>(locs, out);
}